// round 10
// baseline (speedup 1.0000x reference)
#include <cuda_runtime.h>

// Problem-fixed sizes (from setup_inputs)
#define BATCH 8
#define NH 778      // hand verts
#define FH 1538     // hand faces
#define NO 2000     // obj verts
#define FO 4000     // obj faces

#define TOLF    1e-7f
#define DETEPS  1e-8f   // float32(0.1 * TOL)
#define THRESH  25.0f

// Fixed ray direction (float32 of reference constants)
#define RDX 0.4395064455f
#define RDY 0.617598629942f
#define RDZ 0.652231566745f

// Raycast tiling
#define PT   4            // points per thread
#define RTPB 128          // threads per block
#define PPB  (PT*RTPB)    // 512 points per block
#define TCH  128          // triangles per smem stage
#define PB_O ((NO + PPB - 1) / PPB)   // 4
#define PB_H ((NH + PPB - 1) / PPB)   // 2
#define TB_O ((FH + TCH - 1) / TCH)   // 13
#define TB_H ((FO + TCH - 1) / TCH)   // 32
#define BLKS_O (BATCH * PB_O * TB_O)  // 416
#define BLKS_H (BATCH * PB_H * TB_H)  // 512

// Closest tiling: 4 queries/thread, 128-candidate chunks (one smem stage/block)
#define CQB_H ((NH + PPB - 1) / PPB)  // 2
#define CQB_O ((NO + PPB - 1) / PPB)  // 4
#define CCH_O ((NO + TCH - 1) / TCH)  // 16 candidate chunks (obj cands)
#define CCH_H ((NH + TCH - 1) / TCH)  // 7  candidate chunks (hand cands)
#define CBLK_A (BATCH * CQB_H * CCH_O)  // 256
#define CBLK_B (BATCH * CQB_O * CCH_H)  // 224

#define WORK_BLKS (BLKS_O + BLKS_H + CBLK_A + CBLK_B)  // 1408

// Scratch (no allocations allowed)
// Triangle affine forms, 3x float4 per triangle:
//  q0=(nu,cu): u = p.nu - cu ; q1=(nv,cv): v = p.nv - cv
//  q2=(nt,ct'): t' = p.nt - ct' > 0  <=>  t > TOLF   (TOLF folded into ct')
__device__ float4   d_htri[BATCH * FH * 3];
__device__ float4   d_otri[BATCH * FO * 3];
__device__ int      d_hits_o[BATCH * NO];
__device__ int      d_hits_h[BATCH * NH];
__device__ unsigned d_best_h[BATCH * NH];  // orderable-uint of min d' = 0.5*ry - zz
__device__ unsigned d_best_o[BATCH * NO];
__device__ float    d_part[BATCH * 6];
__device__ unsigned d_tick;

__device__ __forceinline__ unsigned ford(float f) {
    unsigned u = __float_as_uint(f);
    return (u & 0x80000000u) ? ~u : (u | 0x80000000u);
}
__device__ __forceinline__ float funord(unsigned k) {
    unsigned u = (k & 0x80000000u) ? (k & 0x7fffffffu) : ~k;
    return __uint_as_float(u);
}

// ---------------------------------------------------------------------------
// Prep: triangle affine forms + all scratch zeroing (independent of tri data).
__global__ void prep_fused(const float* __restrict__ hv, const int* __restrict__ hf,
                           const float* __restrict__ ov, const int* __restrict__ of,
                           const int* __restrict__ fsplits) {
    int i = blockIdx.x * blockDim.x + threadIdx.x;
    // zeroing duties
    if (i < BATCH * NO) { d_hits_o[i] = 0; d_best_o[i] = 0xffffffffu; }
    if (i < BATCH * NH) { d_hits_h[i] = 0; d_best_h[i] = 0xffffffffu; }
    if (i == 0) d_tick = 0;

    const float* verts; const int* faces; float4* out;
    bool extra_valid = true;
    if (i < BATCH * FH) {
        int b = i / FH;
        verts = hv + (size_t)b * NH * 3;
        faces = hf + (size_t)i * 3;
        out   = d_htri + (size_t)i * 3;
    } else {
        int j = i - BATCH * FH;
        if (j >= BATCH * FO) return;
        int b = j / FO, f = j - b * FO;
        verts = ov + (size_t)b * NO * 3;
        faces = of + (size_t)j * 3;
        out   = d_otri + (size_t)j * 3;
        extra_valid = (f < fsplits[b]);
    }
    int i0 = faces[0], i1 = faces[1], i2 = faces[2];
    float v0x = verts[i0*3+0], v0y = verts[i0*3+1], v0z = verts[i0*3+2];
    float v1x = verts[i1*3+0], v1y = verts[i1*3+1], v1z = verts[i1*3+2];
    float v2x = verts[i2*3+0], v2y = verts[i2*3+1], v2z = verts[i2*3+2];
    float e1x = v1x - v0x, e1y = v1y - v0y, e1z = v1z - v0z;
    float e2x = v2x - v0x, e2y = v2y - v0y, e2z = v2z - v0z;
    float pvx = RDY * e2z - RDZ * e2y;
    float pvy = RDZ * e2x - RDX * e2z;
    float pvz = RDX * e2y - RDY * e2x;
    float det = e1x * pvx + e1y * pvy + e1z * pvz;
    bool ok = (fabsf(det) >= TOLF) && extra_valid;
    float inv = ok ? 1.0f / (det + DETEPS) : 0.0f;
    float nux = pvx * inv, nuy = pvy * inv, nuz = pvz * inv;
    float cu = v0x * nux + v0y * nuy + v0z * nuz;
    float wx = e1y * RDZ - e1z * RDY;
    float wy = e1z * RDX - e1x * RDZ;
    float wz = e1x * RDY - e1y * RDX;
    float nvx = wx * inv, nvy = wy * inv, nvz = wz * inv;
    float cv = v0x * nvx + v0y * nvy + v0z * nvz;
    float gx = e1y * e2z - e1z * e2y;
    float gy = e1z * e2x - e1x * e2z;
    float gz = e1x * e2y - e1y * e2x;
    float ntx = gx * inv, nty = gy * inv, ntz = gz * inv;
    float ct = v0x * ntx + v0y * nty + v0z * ntz + TOLF;  // TOLF folded in
    out[0] = make_float4(nux, nuy, nuz, cu);
    out[1] = make_float4(nvx, nvy, nvz, cv);
    out[2] = make_float4(ntx, nty, ntz, ct);
}

// ---------------------------------------------------------------------------
// One grid: both parity raycasts AND both nearest-neighbor directions.
__global__ __launch_bounds__(RTPB, 8) void work_kernel(
        const float* __restrict__ hv, const float* __restrict__ ov,
        const int* __restrict__ fsplits, const int* __restrict__ vsplit) {
    __shared__ float4 s[TCH * 3];
    int bid = blockIdx.x;

    if (bid < BLKS_O + BLKS_H) {
        // ----------------- raycast -----------------
        const float* pts; const float4* tb; int* hits;
        int P, t0, t1, pofs;
        if (bid < BLKS_O) {
            int b = bid / (PB_O * TB_O);
            int r = bid - b * (PB_O * TB_O);
            int pblk = r / TB_O, tcb = r - pblk * TB_O;
            pts  = ov + (size_t)b * NO * 3;  P = NO;
            tb   = d_htri + (size_t)b * FH * 3;
            hits = d_hits_o + b * NO;
            t0 = tcb * TCH; t1 = min(t0 + TCH, FH);
            pofs = pblk * PPB;
        } else {
            int r2 = bid - BLKS_O;
            int b = r2 / (PB_H * TB_H);
            int r = r2 - b * (PB_H * TB_H);
            int pblk = r / TB_H, tcb = r - pblk * TB_H;
            pts  = hv + (size_t)b * NH * 3;  P = NH;
            tb   = d_otri + (size_t)b * FO * 3;
            hits = d_hits_h + b * NH;
            int lim = fsplits[b];                 // invalid tail is contiguous
            t0 = tcb * TCH; t1 = min(t0 + TCH, lim);
            pofs = pblk * PPB;
            if (t0 >= t1) return;                 // block-uniform early out
        }

        float px[PT], py[PT], pz[PT];
        int cnt[PT]; bool act[PT];
        #pragma unroll
        for (int k = 0; k < PT; k++) {
            int p = pofs + k * RTPB + threadIdx.x;
            act[k] = p < P;
            int pc = act[k] ? p : 0;
            px[k] = pts[pc*3+0]; py[k] = pts[pc*3+1]; pz[k] = pts[pc*3+2];
            cnt[k] = 0;
        }
        int n = t1 - t0;
        if (threadIdx.x < n) {
            const float4* src = tb + (size_t)(t0 + threadIdx.x) * 3;
            s[threadIdx.x*3+0] = src[0];
            s[threadIdx.x*3+1] = src[1];
            s[threadIdx.x*3+2] = src[2];
        }
        __syncthreads();
        for (int j = 0; j < n; j++) {
            float4 q0 = s[j*3+0], q1 = s[j*3+1], q2 = s[j*3+2];
            #pragma unroll
            for (int k = 0; k < PT; k++) {
                float u = fmaf(pz[k], q0.z, fmaf(py[k], q0.y, fmaf(px[k], q0.x, -q0.w)));
                float v = fmaf(pz[k], q1.z, fmaf(py[k], q1.y, fmaf(px[k], q1.x, -q1.w)));
                float t = fmaf(pz[k], q2.z, fmaf(py[k], q2.y, fmaf(px[k], q2.x, -q2.w)));
                float m = fminf(fminf(u, v), t);      // all must be > 0
                float sgn = u + v;                    // and u+v < 1
                bool hit = (m > 0.0f) & (sgn < 1.0f); // invalid tris: u=v=0,t=-TOLF -> miss
                cnt[k] += hit ? 1 : 0;
            }
        }
        #pragma unroll
        for (int k = 0; k < PT; k++) {
            if (act[k] && cnt[k])
                atomicAdd(&hits[pofs + k * RTPB + threadIdx.x], cnt[k]);
        }
    } else {
        // ----------------- nearest neighbor (min of d' = 0.5|c|^2 - q.c) ----
        int cb = bid - (BLKS_O + BLKS_H);
        const float* qpts; const float* cpts;
        unsigned* best; int Q, qofs, c0, c1, Svalid;
        if (cb < CBLK_A) {
            // hand queries vs valid obj candidates
            int b = cb / (CQB_H * CCH_O);
            int r = cb - b * (CQB_H * CCH_O);
            int qb = r / CCH_O, ck = r - qb * CCH_O;
            int S = vsplit[b];
            c0 = ck * TCH; c1 = min(c0 + TCH, S);
            if (c0 >= c1) return;
            qpts = hv + (size_t)b * NH * 3; Q = NH; Svalid = NH;
            cpts = ov + (size_t)b * NO * 3;
            best = d_best_h + b * NH;
            qofs = qb * PPB;
        } else {
            // obj queries (valid only) vs all hand candidates
            int r2 = cb - CBLK_A;
            int b = r2 / (CQB_O * CCH_H);
            int r = r2 - b * (CQB_O * CCH_H);
            int qb = r / CCH_H, ck = r - qb * CCH_H;
            c0 = ck * TCH; c1 = min(c0 + TCH, NH);
            qpts = ov + (size_t)b * NO * 3; Q = NO; Svalid = vsplit[b];
            cpts = hv + (size_t)b * NH * 3;
            best = d_best_o + b * NO;
            qofs = qb * PPB;
        }
        float qx[PT], qy[PT], qz[PT], bst[PT];
        bool act[PT];
        #pragma unroll
        for (int k = 0; k < PT; k++) {
            int q = qofs + k * RTPB + threadIdx.x;
            act[k] = (q < Q) && (q < Svalid);
            int qc = (q < Q) ? q : 0;
            qx[k] = -qpts[qc*3+0]; qy[k] = -qpts[qc*3+1]; qz[k] = -qpts[qc*3+2];
            bst[k] = 3.4e38f;
        }
        int cntc = c1 - c0;
        if (threadIdx.x < cntc) {
            const float* c = cpts + (size_t)(c0 + threadIdx.x) * 3;
            float cx = c[0], cy = c[1], cz = c[2];
            s[threadIdx.x] = make_float4(cx, cy, cz, 0.5f*(cx*cx + cy*cy + cz*cz));
        }
        __syncthreads();
        for (int j = 0; j < cntc; j++) {
            float4 c = s[j];
            #pragma unroll
            for (int k = 0; k < PT; k++) {
                float d = fmaf(qz[k], c.z, fmaf(qy[k], c.y, fmaf(qx[k], c.x, c.w)));
                bst[k] = fminf(bst[k], d);
            }
        }
        #pragma unroll
        for (int k = 0; k < PT; k++) {
            if (act[k])
                atomicMin(&best[qofs + k * RTPB + threadIdx.x], ford(bst[k]));
        }
    }
}

// ---------------------------------------------------------------------------
// Per-batch reduction: recompute values from min-metric, masked sums,
// per-batch outputs; ticketed last block writes the global means.
__global__ void reduce_all(const float* __restrict__ hv,
                           const float* __restrict__ ov,
                           const int* __restrict__ vsplit,
                           float* __restrict__ out) {
    __shared__ float sm[8][6];
    int b = blockIdx.x;
    float s1 = 0, c1 = 0, s2 = 0, c2 = 0, s3 = 0, c3 = 0;
    for (int n = threadIdx.x; n < NH; n += blockDim.x) {
        const float* h = hv + ((size_t)b * NH + n) * 3;
        float rx = h[0]*h[0] + h[1]*h[1] + h[2]*h[2];
        float dp = funord(d_best_h[b * NH + n]);   // min(0.5*ry - zz)
        float a = sqrtf(fmaxf(fmaf(2.0f, dp, rx), 0.0f));
        float v = THRESH * tanhf(a / THRESH);
        bool ext = (d_hits_h[b * NH + n] & 1) == 0;
        if (ext) { s1 += v; c1 += 1.f; }
        else     { s2 += v; c2 += 1.f; }
    }
    int S = vsplit[b];
    for (int m = threadIdx.x; m < S; m += blockDim.x) {
        bool inpen = (d_hits_o[b * NO + m] & 1) != 0;
        if (inpen) {
            const float* o = ov + ((size_t)b * NO + m) * 3;
            float ry = o[0]*o[0] + o[1]*o[1] + o[2]*o[2];
            float dp = funord(d_best_o[b * NO + m]);
            float a = sqrtf(fmaxf(fmaf(2.0f, dp, ry), 0.0f));
            s3 += THRESH * tanhf(a / THRESH); c3 += 1.f;
        }
    }
    #pragma unroll
    for (int off = 16; off; off >>= 1) {
        s1 += __shfl_down_sync(0xffffffffu, s1, off);
        c1 += __shfl_down_sync(0xffffffffu, c1, off);
        s2 += __shfl_down_sync(0xffffffffu, s2, off);
        c2 += __shfl_down_sync(0xffffffffu, c2, off);
        s3 += __shfl_down_sync(0xffffffffu, s3, off);
        c3 += __shfl_down_sync(0xffffffffu, c3, off);
    }
    int w = threadIdx.x >> 5;
    if ((threadIdx.x & 31) == 0) {
        sm[w][0] = s1; sm[w][1] = c1; sm[w][2] = s2;
        sm[w][3] = c2; sm[w][4] = s3; sm[w][5] = c3;
    }
    __syncthreads();
    if (threadIdx.x == 0) {
        for (int i = 1; i < (int)(blockDim.x >> 5); i++) {
            s1 += sm[i][0]; c1 += sm[i][1]; s2 += sm[i][2];
            c2 += sm[i][3]; s3 += sm[i][4]; c3 += sm[i][5];
        }
        float missed_b = (c1 > 0.f) ? s1 / fmaxf(c1, 1.0f) : 0.0f;
        float ph_b     = (c2 > 0.f) ? s2 / fmaxf(c2, 1.0f) : 0.0f;
        float po_b     = (c3 > 0.f) ? s3 / fmaxf(c3, 1.0f) : 0.0f;
        out[2 + b]  = missed_b;
        out[10 + b] = ph_b + po_b;
        d_part[b*6+0] = s1; d_part[b*6+1] = c1;
        d_part[b*6+2] = s2; d_part[b*6+3] = c2;
        d_part[b*6+4] = s3; d_part[b*6+5] = c3;
        __threadfence();
        unsigned t = atomicAdd(&d_tick, 1u);
        if (t == BATCH - 1) {   // last block: global means
            float Sm = 0, Cm = 0, Sh = 0, Ch = 0, So = 0, Co = 0;
            for (int bb = 0; bb < BATCH; bb++) {
                Sm += d_part[bb*6+0]; Cm += d_part[bb*6+1];
                Sh += d_part[bb*6+2]; Ch += d_part[bb*6+3];
                So += d_part[bb*6+4]; Co += d_part[bb*6+5];
            }
            float missed_loss = (Cm > 0.f) ? Sm / fmaxf(Cm, 1.0f) : 0.0f;
            float ph_loss     = (Ch > 0.f) ? Sh / fmaxf(Ch, 1.0f) : 0.0f;
            float po_loss     = (Co > 0.f) ? So / fmaxf(Co, 1.0f) : 0.0f;
            out[0] = missed_loss;
            out[1] = ph_loss + po_loss;
        }
    }
}

// ---------------------------------------------------------------------------
extern "C" void kernel_launch(void* const* d_in, const int* in_sizes, int n_in,
                              void* d_out, int out_size) {
    const float* hand_verts = (const float*)d_in[0];
    const int*   hand_faces = (const int*)d_in[1];
    const float* obj_verts  = (const float*)d_in[2];
    const int*   obj_faces  = (const int*)d_in[3];
    const int*   vsplits    = (const int*)d_in[4];
    const int*   fsplits    = (const int*)d_in[5];
    float* out = (float*)d_out;

    prep_fused<<<(BATCH * (FH + FO) + 127) / 128, 128>>>(
        hand_verts, hand_faces, obj_verts, obj_faces, fsplits);
    work_kernel<<<WORK_BLKS, RTPB>>>(hand_verts, obj_verts, fsplits, vsplits);
    reduce_all<<<BATCH, 256>>>(hand_verts, obj_verts, vsplits, out);
}

// round 11
// speedup vs baseline: 1.3797x; 1.3797x over previous
#include <cuda_runtime.h>

// Problem-fixed sizes (from setup_inputs)
#define BATCH 8
#define NH 778      // hand verts
#define FH 1538     // hand faces
#define NO 2000     // obj verts
#define FO 4000     // obj faces

#define TOLF    1e-7f
#define DETEPS  1e-8f   // float32(0.1 * TOL)
#define THRESH  25.0f

// Fixed ray direction (float32 of reference constants)
#define RDX 0.4395064455f
#define RDY 0.617598629942f
#define RDZ 0.652231566745f

// Raycast tiling (identical to the 78.3us configuration)
#define PT   4            // points per thread
#define RTPB 128          // threads per block
#define PPB  (PT*RTPB)    // 512 points per block
#define TCH  128          // triangles per smem stage
#define PB_O ((NO + PPB - 1) / PPB)   // 4
#define PB_H ((NH + PPB - 1) / PPB)   // 2
#define TB_O ((FH + TCH - 1) / TCH)   // 13
#define TB_H ((FO + TCH - 1) / TCH)   // 32
#define BLKS_O (BATCH * PB_O * TB_O)  // 416
#define BLKS_H (BATCH * PB_H * TB_H)  // 512

// Closest tiling: 4 queries/thread, 128-candidate chunk per block
#define CQB_H ((NH + PPB - 1) / PPB)  // 2
#define CQB_O ((NO + PPB - 1) / PPB)  // 4
#define CCH_O ((NO + TCH - 1) / TCH)  // 16
#define CCH_H ((NH + TCH - 1) / TCH)  // 7
#define CBLK_A (BATCH * CQB_H * CCH_O)  // 256
#define CBLK_B (BATCH * CQB_O * CCH_H)  // 224

// Scratch (no allocations allowed)
// Triangle affine forms, 3x float4 per triangle:
//  q0=(nu,cu): u = p.nu - cu ; q1=(nv,cv): v = p.nv - cv
//  q2=(nt,ct'): t' = p.nt - ct' > 0  <=>  t > TOLF   (TOLF folded into ct')
__device__ float4   d_htri[BATCH * FH * 3];
__device__ float4   d_otri[BATCH * FO * 3];
__device__ int      d_hits_o[BATCH * NO];
__device__ int      d_hits_h[BATCH * NH];
__device__ unsigned d_best_h[BATCH * NH];  // orderable-uint of min d' = 0.5*ry - zz
__device__ unsigned d_best_o[BATCH * NO];
__device__ float    d_part[BATCH * 6];
__device__ unsigned d_tick;

__device__ __forceinline__ unsigned ford(float f) {
    unsigned u = __float_as_uint(f);
    return (u & 0x80000000u) ? ~u : (u | 0x80000000u);
}
__device__ __forceinline__ float funord(unsigned k) {
    unsigned u = (k & 0x80000000u) ? (k & 0x7fffffffu) : ~k;
    return __uint_as_float(u);
}

// ---------------------------------------------------------------------------
// Triangle affine-form computation for one global triangle index.
__device__ __forceinline__ void prep_one(int i,
        const float* __restrict__ hv, const int* __restrict__ hf,
        const float* __restrict__ ov, const int* __restrict__ of,
        const int* __restrict__ fsplits) {
    const float* verts; const int* faces; float4* out;
    bool extra_valid = true;
    if (i < BATCH * FH) {
        int b = i / FH;
        verts = hv + (size_t)b * NH * 3;
        faces = hf + (size_t)i * 3;
        out   = d_htri + (size_t)i * 3;
    } else {
        int j = i - BATCH * FH;
        if (j >= BATCH * FO) return;
        int b = j / FO, f = j - b * FO;
        verts = ov + (size_t)b * NO * 3;
        faces = of + (size_t)j * 3;
        out   = d_otri + (size_t)j * 3;
        extra_valid = (f < fsplits[b]);
    }
    int i0 = faces[0], i1 = faces[1], i2 = faces[2];
    float v0x = verts[i0*3+0], v0y = verts[i0*3+1], v0z = verts[i0*3+2];
    float v1x = verts[i1*3+0], v1y = verts[i1*3+1], v1z = verts[i1*3+2];
    float v2x = verts[i2*3+0], v2y = verts[i2*3+1], v2z = verts[i2*3+2];
    float e1x = v1x - v0x, e1y = v1y - v0y, e1z = v1z - v0z;
    float e2x = v2x - v0x, e2y = v2y - v0y, e2z = v2z - v0z;
    float pvx = RDY * e2z - RDZ * e2y;
    float pvy = RDZ * e2x - RDX * e2z;
    float pvz = RDX * e2y - RDY * e2x;
    float det = e1x * pvx + e1y * pvy + e1z * pvz;
    bool ok = (fabsf(det) >= TOLF) && extra_valid;
    float inv = ok ? 1.0f / (det + DETEPS) : 0.0f;
    float nux = pvx * inv, nuy = pvy * inv, nuz = pvz * inv;
    float cu = v0x * nux + v0y * nuy + v0z * nuz;
    float wx = e1y * RDZ - e1z * RDY;
    float wy = e1z * RDX - e1x * RDZ;
    float wz = e1x * RDY - e1y * RDX;
    float nvx = wx * inv, nvy = wy * inv, nvz = wz * inv;
    float cv = v0x * nvx + v0y * nvy + v0z * nvz;
    float gx = e1y * e2z - e1z * e2y;
    float gy = e1z * e2x - e1x * e2z;
    float gz = e1x * e2y - e1y * e2x;
    float ntx = gx * inv, nty = gy * inv, ntz = gz * inv;
    float ct = v0x * ntx + v0y * nty + v0z * ntz + TOLF;  // TOLF folded in
    out[0] = make_float4(nux, nuy, nuz, cu);
    out[1] = make_float4(nvx, nvy, nvz, cv);
    out[2] = make_float4(ntx, nty, ntz, ct);
}

// Prep: 2 triangles per thread (doubles load MLP; kernel is latency-bound)
// plus all scratch zeroing.
__global__ void prep_fused(const float* __restrict__ hv, const int* __restrict__ hf,
                           const float* __restrict__ ov, const int* __restrict__ of,
                           const int* __restrict__ fsplits) {
    int tid = blockIdx.x * blockDim.x + threadIdx.x;
    if (tid < BATCH * NO) { d_hits_o[tid] = 0; d_best_o[tid] = 0xffffffffu; }
    if (tid < BATCH * NH) { d_hits_h[tid] = 0; d_best_h[tid] = 0xffffffffu; }
    if (tid == 0) d_tick = 0;
    int i0 = tid * 2;
    prep_one(i0,     hv, hf, ov, of, fsplits);
    prep_one(i0 + 1, hv, hf, ov, of, fsplits);
}

// ---------------------------------------------------------------------------
// Parity raycast (proven config): 4 points/thread, one 128-tri smem stage.
__global__ __launch_bounds__(RTPB, 8) void raycast_fused(
        const float* __restrict__ hv, const float* __restrict__ ov,
        const int* __restrict__ fsplits) {
    __shared__ float4 s[TCH * 3];
    int bid = blockIdx.x;
    const float* pts; const float4* tb; int* hits;
    int P, t0, t1, pofs;
    if (bid < BLKS_O) {
        int b = bid / (PB_O * TB_O);
        int r = bid - b * (PB_O * TB_O);
        int pblk = r / TB_O, tcb = r - pblk * TB_O;
        pts  = ov + (size_t)b * NO * 3;  P = NO;
        tb   = d_htri + (size_t)b * FH * 3;
        hits = d_hits_o + b * NO;
        t0 = tcb * TCH; t1 = min(t0 + TCH, FH);
        pofs = pblk * PPB;
    } else {
        int r2 = bid - BLKS_O;
        int b = r2 / (PB_H * TB_H);
        int r = r2 - b * (PB_H * TB_H);
        int pblk = r / TB_H, tcb = r - pblk * TB_H;
        pts  = hv + (size_t)b * NH * 3;  P = NH;
        tb   = d_otri + (size_t)b * FO * 3;
        hits = d_hits_h + b * NH;
        int lim = fsplits[b];                 // invalid tail is contiguous
        t0 = tcb * TCH; t1 = min(t0 + TCH, lim);
        pofs = pblk * PPB;
        if (t0 >= t1) return;                 // block-uniform early out
    }

    float px[PT], py[PT], pz[PT];
    int cnt[PT]; bool act[PT];
    #pragma unroll
    for (int k = 0; k < PT; k++) {
        int p = pofs + k * RTPB + threadIdx.x;
        act[k] = p < P;
        int pc = act[k] ? p : 0;
        px[k] = pts[pc*3+0]; py[k] = pts[pc*3+1]; pz[k] = pts[pc*3+2];
        cnt[k] = 0;
    }
    int n = t1 - t0;
    if (threadIdx.x < n) {
        const float4* src = tb + (size_t)(t0 + threadIdx.x) * 3;
        s[threadIdx.x*3+0] = src[0];
        s[threadIdx.x*3+1] = src[1];
        s[threadIdx.x*3+2] = src[2];
    }
    __syncthreads();
    for (int j = 0; j < n; j++) {
        float4 q0 = s[j*3+0], q1 = s[j*3+1], q2 = s[j*3+2];
        #pragma unroll
        for (int k = 0; k < PT; k++) {
            float u = fmaf(pz[k], q0.z, fmaf(py[k], q0.y, fmaf(px[k], q0.x, -q0.w)));
            float v = fmaf(pz[k], q1.z, fmaf(py[k], q1.y, fmaf(px[k], q1.x, -q1.w)));
            float t = fmaf(pz[k], q2.z, fmaf(py[k], q2.y, fmaf(px[k], q2.x, -q2.w)));
            float m = fminf(fminf(u, v), t);           // all must be > 0
            float m2 = fminf(m, 1.0f - (u + v));       // and u+v < 1
            cnt[k] += (m2 > 0.0f) ? 1 : 0;             // invalid tris -> u=v=0 -> miss
        }
    }
    #pragma unroll
    for (int k = 0; k < PT; k++) {
        if (act[k] && cnt[k])
            atomicAdd(&hits[pofs + k * RTPB + threadIdx.x], cnt[k]);
    }
}

// ---------------------------------------------------------------------------
// Nearest neighbor, both directions, register-tiled (4 queries/thread),
// min over metric d' = 0.5|c|^2 - q.c (argmin index not needed).
__global__ __launch_bounds__(RTPB) void closest_fused(
        const float* __restrict__ hv, const float* __restrict__ ov,
        const int* __restrict__ vsplit) {
    __shared__ float4 s[TCH];
    int cb = blockIdx.x;
    const float* qpts; const float* cpts;
    unsigned* best; int Q, qofs, c0, c1, Svalid;
    if (cb < CBLK_A) {
        // hand queries vs valid obj candidates
        int b = cb / (CQB_H * CCH_O);
        int r = cb - b * (CQB_H * CCH_O);
        int qb = r / CCH_O, ck = r - qb * CCH_O;
        int S = vsplit[b];
        c0 = ck * TCH; c1 = min(c0 + TCH, S);
        if (c0 >= c1) return;
        qpts = hv + (size_t)b * NH * 3; Q = NH; Svalid = NH;
        cpts = ov + (size_t)b * NO * 3;
        best = d_best_h + b * NH;
        qofs = qb * PPB;
    } else {
        // obj queries (valid only) vs all hand candidates
        int r2 = cb - CBLK_A;
        int b = r2 / (CQB_O * CCH_H);
        int r = r2 - b * (CQB_O * CCH_H);
        int qb = r / CCH_H, ck = r - qb * CCH_H;
        c0 = ck * TCH; c1 = min(c0 + TCH, NH);
        qpts = ov + (size_t)b * NO * 3; Q = NO; Svalid = vsplit[b];
        cpts = hv + (size_t)b * NH * 3;
        best = d_best_o + b * NO;
        qofs = qb * PPB;
    }
    float qx[PT], qy[PT], qz[PT], bst[PT];
    bool act[PT];
    #pragma unroll
    for (int k = 0; k < PT; k++) {
        int q = qofs + k * RTPB + threadIdx.x;
        act[k] = (q < Q) && (q < Svalid);
        int qc = (q < Q) ? q : 0;
        qx[k] = -qpts[qc*3+0]; qy[k] = -qpts[qc*3+1]; qz[k] = -qpts[qc*3+2];
        bst[k] = 3.4e38f;
    }
    int cntc = c1 - c0;
    if (threadIdx.x < cntc) {
        const float* c = cpts + (size_t)(c0 + threadIdx.x) * 3;
        float cx = c[0], cy = c[1], cz = c[2];
        s[threadIdx.x] = make_float4(cx, cy, cz, 0.5f*(cx*cx + cy*cy + cz*cz));
    }
    __syncthreads();
    for (int j = 0; j < cntc; j++) {
        float4 c = s[j];
        #pragma unroll
        for (int k = 0; k < PT; k++) {
            float d = fmaf(qz[k], c.z, fmaf(qy[k], c.y, fmaf(qx[k], c.x, c.w)));
            bst[k] = fminf(bst[k], d);
        }
    }
    #pragma unroll
    for (int k = 0; k < PT; k++) {
        if (act[k])
            atomicMin(&best[qofs + k * RTPB + threadIdx.x], ford(bst[k]));
    }
}

// ---------------------------------------------------------------------------
// Per-batch reduction: recompute anchor dists from min-metric, masked sums,
// per-batch outputs; ticketed last block writes the global means.
__global__ void reduce_all(const float* __restrict__ hv,
                           const float* __restrict__ ov,
                           const int* __restrict__ vsplit,
                           float* __restrict__ out) {
    __shared__ float sm[8][6];
    int b = blockIdx.x;
    float s1 = 0, c1 = 0, s2 = 0, c2 = 0, s3 = 0, c3 = 0;
    for (int n = threadIdx.x; n < NH; n += blockDim.x) {
        const float* h = hv + ((size_t)b * NH + n) * 3;
        float rx = h[0]*h[0] + h[1]*h[1] + h[2]*h[2];
        float dp = funord(d_best_h[b * NH + n]);   // min(0.5*ry - zz)
        float a = sqrtf(fmaxf(fmaf(2.0f, dp, rx), 0.0f));
        float v = THRESH * tanhf(a / THRESH);
        bool ext = (d_hits_h[b * NH + n] & 1) == 0;
        if (ext) { s1 += v; c1 += 1.f; }
        else     { s2 += v; c2 += 1.f; }
    }
    int S = vsplit[b];
    for (int m = threadIdx.x; m < S; m += blockDim.x) {
        bool inpen = (d_hits_o[b * NO + m] & 1) != 0;
        if (inpen) {
            const float* o = ov + ((size_t)b * NO + m) * 3;
            float ry = o[0]*o[0] + o[1]*o[1] + o[2]*o[2];
            float dp = funord(d_best_o[b * NO + m]);
            float a = sqrtf(fmaxf(fmaf(2.0f, dp, ry), 0.0f));
            s3 += THRESH * tanhf(a / THRESH); c3 += 1.f;
        }
    }
    #pragma unroll
    for (int off = 16; off; off >>= 1) {
        s1 += __shfl_down_sync(0xffffffffu, s1, off);
        c1 += __shfl_down_sync(0xffffffffu, c1, off);
        s2 += __shfl_down_sync(0xffffffffu, s2, off);
        c2 += __shfl_down_sync(0xffffffffu, c2, off);
        s3 += __shfl_down_sync(0xffffffffu, s3, off);
        c3 += __shfl_down_sync(0xffffffffu, c3, off);
    }
    int w = threadIdx.x >> 5;
    if ((threadIdx.x & 31) == 0) {
        sm[w][0] = s1; sm[w][1] = c1; sm[w][2] = s2;
        sm[w][3] = c2; sm[w][4] = s3; sm[w][5] = c3;
    }
    __syncthreads();
    if (threadIdx.x == 0) {
        for (int i = 1; i < (int)(blockDim.x >> 5); i++) {
            s1 += sm[i][0]; c1 += sm[i][1]; s2 += sm[i][2];
            c2 += sm[i][3]; s3 += sm[i][4]; c3 += sm[i][5];
        }
        float missed_b = (c1 > 0.f) ? s1 / fmaxf(c1, 1.0f) : 0.0f;
        float ph_b     = (c2 > 0.f) ? s2 / fmaxf(c2, 1.0f) : 0.0f;
        float po_b     = (c3 > 0.f) ? s3 / fmaxf(c3, 1.0f) : 0.0f;
        out[2 + b]  = missed_b;
        out[10 + b] = ph_b + po_b;
        d_part[b*6+0] = s1; d_part[b*6+1] = c1;
        d_part[b*6+2] = s2; d_part[b*6+3] = c2;
        d_part[b*6+4] = s3; d_part[b*6+5] = c3;
        __threadfence();
        unsigned t = atomicAdd(&d_tick, 1u);
        if (t == BATCH - 1) {   // last block: global means
            float Sm = 0, Cm = 0, Sh = 0, Ch = 0, So = 0, Co = 0;
            for (int bb = 0; bb < BATCH; bb++) {
                Sm += d_part[bb*6+0]; Cm += d_part[bb*6+1];
                Sh += d_part[bb*6+2]; Ch += d_part[bb*6+3];
                So += d_part[bb*6+4]; Co += d_part[bb*6+5];
            }
            float missed_loss = (Cm > 0.f) ? Sm / fmaxf(Cm, 1.0f) : 0.0f;
            float ph_loss     = (Ch > 0.f) ? Sh / fmaxf(Ch, 1.0f) : 0.0f;
            float po_loss     = (Co > 0.f) ? So / fmaxf(Co, 1.0f) : 0.0f;
            out[0] = missed_loss;
            out[1] = ph_loss + po_loss;
        }
    }
}

// ---------------------------------------------------------------------------
extern "C" void kernel_launch(void* const* d_in, const int* in_sizes, int n_in,
                              void* d_out, int out_size) {
    const float* hand_verts = (const float*)d_in[0];
    const int*   hand_faces = (const int*)d_in[1];
    const float* obj_verts  = (const float*)d_in[2];
    const int*   obj_faces  = (const int*)d_in[3];
    const int*   vsplits    = (const int*)d_in[4];
    const int*   fsplits    = (const int*)d_in[5];
    float* out = (float*)d_out;

    prep_fused<<<(BATCH * (FH + FO) / 2 + 127) / 128, 128>>>(
        hand_verts, hand_faces, obj_verts, obj_faces, fsplits);
    raycast_fused<<<BLKS_O + BLKS_H, RTPB>>>(hand_verts, obj_verts, fsplits);
    closest_fused<<<CBLK_A + CBLK_B, RTPB>>>(hand_verts, obj_verts, vsplits);
    reduce_all<<<BATCH, 256>>>(hand_verts, obj_verts, vsplits, out);
}

// round 12
// speedup vs baseline: 1.4754x; 1.0693x over previous
#include <cuda_runtime.h>

// Problem-fixed sizes (from setup_inputs)
#define BATCH 8
#define NH 778      // hand verts
#define FH 1538     // hand faces
#define NO 2000     // obj verts
#define FO 4000     // obj faces

#define TOLF    1e-7f
#define DETEPS  1e-8f   // float32(0.1 * TOL)
#define THRESH  25.0f

// Fixed ray direction (float32 of reference constants)
#define RDX 0.4395064455f
#define RDY 0.617598629942f
#define RDZ 0.652231566745f

// Raycast tiling (proven 68us configuration)
#define PT   4            // points per thread
#define RTPB 128          // threads per block
#define PPB  (PT*RTPB)    // 512 points per block
#define TCH  128          // triangles per smem stage
#define PB_O ((NO + PPB - 1) / PPB)   // 4
#define PB_H ((NH + PPB - 1) / PPB)   // 2
#define TB_O ((FH + TCH - 1) / TCH)   // 13
#define TB_H ((FO + TCH - 1) / TCH)   // 32
#define BLKS_O (BATCH * PB_O * TB_O)  // 416
#define BLKS_H (BATCH * PB_H * TB_H)  // 512

// Closest tiling: 4 queries/thread, 128-candidate chunk per block
#define CQB_H ((NH + PPB - 1) / PPB)  // 2
#define CQB_O ((NO + PPB - 1) / PPB)  // 4
#define CCH_O ((NO + TCH - 1) / TCH)  // 16
#define CCH_H ((NH + TCH - 1) / TCH)  // 7
#define CBLK_A (BATCH * CQB_H * CCH_O)  // 256
#define CBLK_B (BATCH * CQB_O * CCH_H)  // 224

// Reduction tiling: 8 slices per batch over the combined (NH + NO) range
#define RSL   8
#define RITEMS (NH + NO)                         // 2778
#define RCH   ((RITEMS + RSL - 1) / RSL)         // 348
#define RBLKS (BATCH * RSL)                      // 64

// Scratch (no allocations allowed)
// Triangle affine forms, 3x float4 per triangle:
//  q0=(nu,cu): u = p.nu - cu ; q1=(nv,cv): v = p.nv - cv
//  q2=(nt,ct'): t' = p.nt - ct' > 0  <=>  t > TOLF   (TOLF folded into ct')
__device__ float4   d_htri[BATCH * FH * 3];
__device__ float4   d_otri[BATCH * FO * 3];
__device__ int      d_hits_o[BATCH * NO];
__device__ int      d_hits_h[BATCH * NH];
__device__ unsigned d_best_h[BATCH * NH];  // orderable-uint of min d' = 0.5*ry - zz
__device__ unsigned d_best_o[BATCH * NO];
__device__ float    d_part[BATCH * 6];
__device__ unsigned d_tick;

__device__ __forceinline__ unsigned ford(float f) {
    unsigned u = __float_as_uint(f);
    return (u & 0x80000000u) ? ~u : (u | 0x80000000u);
}
__device__ __forceinline__ float funord(unsigned k) {
    unsigned u = (k & 0x80000000u) ? (k & 0x7fffffffu) : ~k;
    return __uint_as_float(u);
}

// ---------------------------------------------------------------------------
// Triangle affine-form computation for one global triangle index.
__device__ __forceinline__ void prep_one(int i,
        const float* __restrict__ hv, const int* __restrict__ hf,
        const float* __restrict__ ov, const int* __restrict__ of,
        const int* __restrict__ fsplits) {
    const float* verts; const int* faces; float4* out;
    bool extra_valid = true;
    if (i < BATCH * FH) {
        int b = i / FH;
        verts = hv + (size_t)b * NH * 3;
        faces = hf + (size_t)i * 3;
        out   = d_htri + (size_t)i * 3;
    } else {
        int j = i - BATCH * FH;
        if (j >= BATCH * FO) return;
        int b = j / FO, f = j - b * FO;
        verts = ov + (size_t)b * NO * 3;
        faces = of + (size_t)j * 3;
        out   = d_otri + (size_t)j * 3;
        extra_valid = (f < fsplits[b]);
    }
    int i0 = faces[0], i1 = faces[1], i2 = faces[2];
    float v0x = verts[i0*3+0], v0y = verts[i0*3+1], v0z = verts[i0*3+2];
    float v1x = verts[i1*3+0], v1y = verts[i1*3+1], v1z = verts[i1*3+2];
    float v2x = verts[i2*3+0], v2y = verts[i2*3+1], v2z = verts[i2*3+2];
    float e1x = v1x - v0x, e1y = v1y - v0y, e1z = v1z - v0z;
    float e2x = v2x - v0x, e2y = v2y - v0y, e2z = v2z - v0z;
    float pvx = RDY * e2z - RDZ * e2y;
    float pvy = RDZ * e2x - RDX * e2z;
    float pvz = RDX * e2y - RDY * e2x;
    float det = e1x * pvx + e1y * pvy + e1z * pvz;
    bool ok = (fabsf(det) >= TOLF) && extra_valid;
    float inv = ok ? 1.0f / (det + DETEPS) : 0.0f;
    float nux = pvx * inv, nuy = pvy * inv, nuz = pvz * inv;
    float cu = v0x * nux + v0y * nuy + v0z * nuz;
    float wx = e1y * RDZ - e1z * RDY;
    float wy = e1z * RDX - e1x * RDZ;
    float wz = e1x * RDY - e1y * RDX;
    float nvx = wx * inv, nvy = wy * inv, nvz = wz * inv;
    float cv = v0x * nvx + v0y * nvy + v0z * nvz;
    float gx = e1y * e2z - e1z * e2y;
    float gy = e1z * e2x - e1x * e2z;
    float gz = e1x * e2y - e1y * e2x;
    float ntx = gx * inv, nty = gy * inv, ntz = gz * inv;
    float ct = v0x * ntx + v0y * nty + v0z * ntz + TOLF;  // TOLF folded in
    out[0] = make_float4(nux, nuy, nuz, cu);
    out[1] = make_float4(nvx, nvy, nvz, cv);
    out[2] = make_float4(ntx, nty, ntz, ct);
}

// Prep: 2 triangles per thread + all scratch zeroing.
__global__ void prep_fused(const float* __restrict__ hv, const int* __restrict__ hf,
                           const float* __restrict__ ov, const int* __restrict__ of,
                           const int* __restrict__ fsplits) {
    int tid = blockIdx.x * blockDim.x + threadIdx.x;
    if (tid < BATCH * NO) { d_hits_o[tid] = 0; d_best_o[tid] = 0xffffffffu; }
    if (tid < BATCH * NH) { d_hits_h[tid] = 0; d_best_h[tid] = 0xffffffffu; }
    if (tid < BATCH * 6)  d_part[tid] = 0.0f;
    if (tid == 0) d_tick = 0;
    int i0 = tid * 2;
    prep_one(i0,     hv, hf, ov, of, fsplits);
    prep_one(i0 + 1, hv, hf, ov, of, fsplits);
}

// ---------------------------------------------------------------------------
// Parity raycast (proven config): 4 points/thread, one 128-tri smem stage.
__global__ __launch_bounds__(RTPB, 8) void raycast_fused(
        const float* __restrict__ hv, const float* __restrict__ ov,
        const int* __restrict__ fsplits) {
    __shared__ float4 s[TCH * 3];
    int bid = blockIdx.x;
    const float* pts; const float4* tb; int* hits;
    int P, t0, t1, pofs;
    if (bid < BLKS_O) {
        int b = bid / (PB_O * TB_O);
        int r = bid - b * (PB_O * TB_O);
        int pblk = r / TB_O, tcb = r - pblk * TB_O;
        pts  = ov + (size_t)b * NO * 3;  P = NO;
        tb   = d_htri + (size_t)b * FH * 3;
        hits = d_hits_o + b * NO;
        t0 = tcb * TCH; t1 = min(t0 + TCH, FH);
        pofs = pblk * PPB;
    } else {
        int r2 = bid - BLKS_O;
        int b = r2 / (PB_H * TB_H);
        int r = r2 - b * (PB_H * TB_H);
        int pblk = r / TB_H, tcb = r - pblk * TB_H;
        pts  = hv + (size_t)b * NH * 3;  P = NH;
        tb   = d_otri + (size_t)b * FO * 3;
        hits = d_hits_h + b * NH;
        int lim = fsplits[b];                 // invalid tail is contiguous
        t0 = tcb * TCH; t1 = min(t0 + TCH, lim);
        pofs = pblk * PPB;
        if (t0 >= t1) return;                 // block-uniform early out
    }

    float px[PT], py[PT], pz[PT];
    int cnt[PT]; bool act[PT];
    #pragma unroll
    for (int k = 0; k < PT; k++) {
        int p = pofs + k * RTPB + threadIdx.x;
        act[k] = p < P;
        int pc = act[k] ? p : 0;
        px[k] = pts[pc*3+0]; py[k] = pts[pc*3+1]; pz[k] = pts[pc*3+2];
        cnt[k] = 0;
    }
    int n = t1 - t0;
    if (threadIdx.x < n) {
        const float4* src = tb + (size_t)(t0 + threadIdx.x) * 3;
        s[threadIdx.x*3+0] = src[0];
        s[threadIdx.x*3+1] = src[1];
        s[threadIdx.x*3+2] = src[2];
    }
    __syncthreads();
    for (int j = 0; j < n; j++) {
        float4 q0 = s[j*3+0], q1 = s[j*3+1], q2 = s[j*3+2];
        #pragma unroll
        for (int k = 0; k < PT; k++) {
            float u = fmaf(pz[k], q0.z, fmaf(py[k], q0.y, fmaf(px[k], q0.x, -q0.w)));
            float v = fmaf(pz[k], q1.z, fmaf(py[k], q1.y, fmaf(px[k], q1.x, -q1.w)));
            float t = fmaf(pz[k], q2.z, fmaf(py[k], q2.y, fmaf(px[k], q2.x, -q2.w)));
            float m = fminf(fminf(u, v), t);           // all must be > 0
            float m2 = fminf(m, 1.0f - (u + v));       // and u+v < 1
            cnt[k] += (m2 > 0.0f) ? 1 : 0;             // invalid tris -> u=v=0 -> miss
        }
    }
    #pragma unroll
    for (int k = 0; k < PT; k++) {
        if (act[k] && cnt[k])
            atomicAdd(&hits[pofs + k * RTPB + threadIdx.x], cnt[k]);
    }
}

// ---------------------------------------------------------------------------
// Nearest neighbor, both directions, register-tiled (4 queries/thread),
// min over metric d' = 0.5|c|^2 - q.c (argmin index not needed).
__global__ __launch_bounds__(RTPB) void closest_fused(
        const float* __restrict__ hv, const float* __restrict__ ov,
        const int* __restrict__ vsplit) {
    __shared__ float4 s[TCH];
    int cb = blockIdx.x;
    const float* qpts; const float* cpts;
    unsigned* best; int Q, qofs, c0, c1, Svalid;
    if (cb < CBLK_A) {
        // hand queries vs valid obj candidates
        int b = cb / (CQB_H * CCH_O);
        int r = cb - b * (CQB_H * CCH_O);
        int qb = r / CCH_O, ck = r - qb * CCH_O;
        int S = vsplit[b];
        c0 = ck * TCH; c1 = min(c0 + TCH, S);
        if (c0 >= c1) return;
        qpts = hv + (size_t)b * NH * 3; Q = NH; Svalid = NH;
        cpts = ov + (size_t)b * NO * 3;
        best = d_best_h + b * NH;
        qofs = qb * PPB;
    } else {
        // obj queries (valid only) vs all hand candidates
        int r2 = cb - CBLK_A;
        int b = r2 / (CQB_O * CCH_H);
        int r = r2 - b * (CQB_O * CCH_H);
        int qb = r / CCH_H, ck = r - qb * CCH_H;
        c0 = ck * TCH; c1 = min(c0 + TCH, NH);
        qpts = ov + (size_t)b * NO * 3; Q = NO; Svalid = vsplit[b];
        cpts = hv + (size_t)b * NH * 3;
        best = d_best_o + b * NO;
        qofs = qb * PPB;
    }
    float qx[PT], qy[PT], qz[PT], bst[PT];
    bool act[PT];
    #pragma unroll
    for (int k = 0; k < PT; k++) {
        int q = qofs + k * RTPB + threadIdx.x;
        act[k] = (q < Q) && (q < Svalid);
        int qc = (q < Q) ? q : 0;
        qx[k] = -qpts[qc*3+0]; qy[k] = -qpts[qc*3+1]; qz[k] = -qpts[qc*3+2];
        bst[k] = 3.4e38f;
    }
    int cntc = c1 - c0;
    if (threadIdx.x < cntc) {
        const float* c = cpts + (size_t)(c0 + threadIdx.x) * 3;
        float cx = c[0], cy = c[1], cz = c[2];
        s[threadIdx.x] = make_float4(cx, cy, cz, 0.5f*(cx*cx + cy*cy + cz*cz));
    }
    __syncthreads();
    for (int j = 0; j < cntc; j++) {
        float4 c = s[j];
        #pragma unroll
        for (int k = 0; k < PT; k++) {
            float d = fmaf(qz[k], c.z, fmaf(qy[k], c.y, fmaf(qx[k], c.x, c.w)));
            bst[k] = fminf(bst[k], d);
        }
    }
    #pragma unroll
    for (int k = 0; k < PT; k++) {
        if (act[k])
            atomicMin(&best[qofs + k * RTPB + threadIdx.x], ford(bst[k]));
    }
}

// ---------------------------------------------------------------------------
// Parallel reduction: 8 slices per batch, partials atomicAdd'ed into d_part;
// ticketed last block computes all 18 outputs.
__global__ void reduce_all(const float* __restrict__ hv,
                           const float* __restrict__ ov,
                           const int* __restrict__ vsplit,
                           float* __restrict__ out) {
    __shared__ float sm[8][6];
    int b  = blockIdx.x / RSL;
    int sl = blockIdx.x - b * RSL;
    int i0 = sl * RCH, i1 = min(i0 + RCH, RITEMS);
    int S = vsplit[b];
    float s1 = 0, c1 = 0, s2 = 0, c2 = 0, s3 = 0, c3 = 0;
    for (int i = i0 + threadIdx.x; i < i1; i += blockDim.x) {
        if (i < NH) {
            int n = i;
            const float* h = hv + ((size_t)b * NH + n) * 3;
            float rx = h[0]*h[0] + h[1]*h[1] + h[2]*h[2];
            float dp = funord(d_best_h[b * NH + n]);   // min(0.5*ry - zz)
            float a = sqrtf(fmaxf(fmaf(2.0f, dp, rx), 0.0f));
            float v = THRESH * tanhf(a / THRESH);
            bool ext = (d_hits_h[b * NH + n] & 1) == 0;
            if (ext) { s1 += v; c1 += 1.f; }
            else     { s2 += v; c2 += 1.f; }
        } else {
            int m = i - NH;
            if (m < S && (d_hits_o[b * NO + m] & 1) != 0) {
                const float* o = ov + ((size_t)b * NO + m) * 3;
                float ry = o[0]*o[0] + o[1]*o[1] + o[2]*o[2];
                float dp = funord(d_best_o[b * NO + m]);
                float a = sqrtf(fmaxf(fmaf(2.0f, dp, ry), 0.0f));
                s3 += THRESH * tanhf(a / THRESH); c3 += 1.f;
            }
        }
    }
    #pragma unroll
    for (int off = 16; off; off >>= 1) {
        s1 += __shfl_down_sync(0xffffffffu, s1, off);
        c1 += __shfl_down_sync(0xffffffffu, c1, off);
        s2 += __shfl_down_sync(0xffffffffu, s2, off);
        c2 += __shfl_down_sync(0xffffffffu, c2, off);
        s3 += __shfl_down_sync(0xffffffffu, s3, off);
        c3 += __shfl_down_sync(0xffffffffu, c3, off);
    }
    int w = threadIdx.x >> 5;
    if ((threadIdx.x & 31) == 0) {
        sm[w][0] = s1; sm[w][1] = c1; sm[w][2] = s2;
        sm[w][3] = c2; sm[w][4] = s3; sm[w][5] = c3;
    }
    __syncthreads();
    if (threadIdx.x == 0) {
        for (int i = 1; i < (int)(blockDim.x >> 5); i++) {
            s1 += sm[i][0]; c1 += sm[i][1]; s2 += sm[i][2];
            c2 += sm[i][3]; s3 += sm[i][4]; c3 += sm[i][5];
        }
        atomicAdd(&d_part[b*6+0], s1); atomicAdd(&d_part[b*6+1], c1);
        atomicAdd(&d_part[b*6+2], s2); atomicAdd(&d_part[b*6+3], c2);
        atomicAdd(&d_part[b*6+4], s3); atomicAdd(&d_part[b*6+5], c3);
        __threadfence();
        unsigned t = atomicAdd(&d_tick, 1u);
        if (t == RBLKS - 1) {   // last block: all outputs
            float Sm = 0, Cm = 0, Sh = 0, Ch = 0, So = 0, Co = 0;
            for (int bb = 0; bb < BATCH; bb++) {
                float p0 = d_part[bb*6+0], p1 = d_part[bb*6+1];
                float p2 = d_part[bb*6+2], p3 = d_part[bb*6+3];
                float p4 = d_part[bb*6+4], p5 = d_part[bb*6+5];
                Sm += p0; Cm += p1; Sh += p2; Ch += p3; So += p4; Co += p5;
                float missed_b = (p1 > 0.f) ? p0 / fmaxf(p1, 1.0f) : 0.0f;
                float ph_b     = (p3 > 0.f) ? p2 / fmaxf(p3, 1.0f) : 0.0f;
                float po_b     = (p5 > 0.f) ? p4 / fmaxf(p5, 1.0f) : 0.0f;
                out[2 + bb]  = missed_b;
                out[10 + bb] = ph_b + po_b;
            }
            float missed_loss = (Cm > 0.f) ? Sm / fmaxf(Cm, 1.0f) : 0.0f;
            float ph_loss     = (Ch > 0.f) ? Sh / fmaxf(Ch, 1.0f) : 0.0f;
            float po_loss     = (Co > 0.f) ? So / fmaxf(Co, 1.0f) : 0.0f;
            out[0] = missed_loss;
            out[1] = ph_loss + po_loss;
        }
    }
}

// ---------------------------------------------------------------------------
extern "C" void kernel_launch(void* const* d_in, const int* in_sizes, int n_in,
                              void* d_out, int out_size) {
    const float* hand_verts = (const float*)d_in[0];
    const int*   hand_faces = (const int*)d_in[1];
    const float* obj_verts  = (const float*)d_in[2];
    const int*   obj_faces  = (const int*)d_in[3];
    const int*   vsplits    = (const int*)d_in[4];
    const int*   fsplits    = (const int*)d_in[5];
    float* out = (float*)d_out;

    prep_fused<<<(BATCH * (FH + FO) / 2 + 127) / 128, 128>>>(
        hand_verts, hand_faces, obj_verts, obj_faces, fsplits);
    raycast_fused<<<BLKS_O + BLKS_H, RTPB>>>(hand_verts, obj_verts, fsplits);
    closest_fused<<<CBLK_A + CBLK_B, RTPB>>>(hand_verts, obj_verts, vsplits);
    reduce_all<<<RBLKS, 256>>>(hand_verts, obj_verts, vsplits, out);
}